// round 8
// baseline (speedup 1.0000x reference)
#include <cuda_runtime.h>

#define N_QUBITS 10
#define TPB 128

// Closed-form evaluation of the 10-qubit staircase circuit:
//   E_0 = cos(x_0 + r_0)
//   E_i = cos(x_i + r_i) * ((1-k_{i-1}) + k_{i-1} * E_{i-1}),  k_j = (1 - cos e_j)/2
// (R0 derivation: each entangling gate is diagonal in its control qubit's Z
// basis, so <Z_i> is fixed after gate (i-1,i); with single-qubit states
// (cos, -i sin) only the diagonal of the 2x2 reduced density matrix
// propagates, collapsing the 2^10 state vector to a 10-step scalar recurrence.)
//
// One sample per thread: 10 floats = 5 aligned float2 (byte offset 40*t).
// No shared memory, no barriers, no guard (grid exactly covers 16384 samples).
// 128 CTAs x 128 threads: single wave, best measured wall — kernel sits on
// the graph-replay/launch floor. Carry step refactored to a single FMA
// (carry = fma(k, ev, 1-k)) to minimize the serial dependency chain.
__global__ void __launch_bounds__(TPB, 1)
qsa_closed_form_kernel(const float2* __restrict__ inputs2,
                       const float* __restrict__ rot,
                       const float* __restrict__ ent,
                       float2* __restrict__ out2) {
    const int t = blockIdx.x * TPB + threadIdx.x;   // sample index, exact fit

    // 5 independent LDG.64 (MLP = 5), issued first.
    float2 v[5];
    const float2* src = inputs2 + t * 5;
    #pragma unroll
    for (int i = 0; i < 5; i++) v[i] = src[i];

    // Uniform broadcast loads of the tiny parameter vectors.
    float r[N_QUBITS], k[N_QUBITS - 1], kc[N_QUBITS - 1];
    #pragma unroll
    for (int i = 0; i < N_QUBITS; i++) r[i] = __ldg(&rot[i]);
    #pragma unroll
    for (int i = 0; i < N_QUBITS - 1; i++) {
        float kk = 0.5f - 0.5f * __cosf(__ldg(&ent[i]));   // sin^2(e/2)
        k[i]  = kk;
        kc[i] = 1.0f - kk;
    }

    float x[N_QUBITS];
    #pragma unroll
    for (int i = 0; i < 5; i++) { x[2*i] = v[i].x; x[2*i+1] = v[i].y; }

    // All 10 cos are independent (pipelined MUFU); carry chain is
    // mul + fma per step (the minimal 2-op serial form).
    float c[N_QUBITS];
    #pragma unroll
    for (int i = 0; i < N_QUBITS; i++) c[i] = __cosf(x[i] + r[i]);

    float e[N_QUBITS];
    float carry = 1.0f;
    #pragma unroll
    for (int i = 0; i < N_QUBITS; i++) {
        float ev = c[i] * carry;
        e[i] = ev;
        if (i < N_QUBITS - 1) carry = __fmaf_rn(k[i], ev, kc[i]);
    }

    float2* dst = out2 + t * 5;
    #pragma unroll
    for (int i = 0; i < 5; i++) {
        float2 o; o.x = e[2*i]; o.y = e[2*i+1];
        dst[i] = o;
    }
}

extern "C" void kernel_launch(void* const* d_in, const int* in_sizes, int n_in,
                              void* d_out, int out_size) {
    const float* inputs = (const float*)d_in[0];  // (16, 1024, 10) fp32
    const float* rot    = (const float*)d_in[1];  // (10,)
    const float* ent    = (const float*)d_in[2];  // (9,)
    float* out = (float*)d_out;

    int total_elems = in_sizes[0];                 // 163840
    int T = total_elems / N_QUBITS;                // 16384 samples
    int blocks = T / TPB;                          // 128, exact

    qsa_closed_form_kernel<<<blocks, TPB>>>(
        reinterpret_cast<const float2*>(inputs), rot, ent,
        reinterpret_cast<float2*>(out));
}

// round 9
// speedup vs baseline: 1.0833x; 1.0833x over previous
#include <cuda_runtime.h>

#define N_QUBITS 10
#define TPB 128

// Closed-form evaluation of the 10-qubit staircase circuit:
//   E_0 = cos(x_0 + r_0)
//   E_i = cos(x_i + r_i) * ((1-k_{i-1}) + k_{i-1} * E_{i-1}),  k_j = (1 - cos e_j)/2
// (R0 derivation: each entangling gate is diagonal in its control qubit's Z
// basis, so <Z_i> is fixed after gate (i-1,i); with single-qubit states
// (cos, -i sin) only the diagonal of the 2x2 reduced density matrix
// propagates, collapsing the 2^10 state vector to a 10-step scalar recurrence.)
//
// One sample per thread: 10 floats = 5 aligned float2 (byte offset 40*t).
// No shared memory, no barriers, no guard (grid exactly covers 16384 samples).
// 128 CTAs x 128 threads, single wave. Parameter vectors fetched with 5
// vector loads (2xLDG.128 + LDG.64 for rot, 2xLDG.128 + LDG.32 for ent)
// instead of 19 scalar LDGs. Carry step is one mul + one FMA (minimal form).
__global__ void __launch_bounds__(TPB, 1)
qsa_closed_form_kernel(const float2* __restrict__ inputs2,
                       const float* __restrict__ rot,
                       const float* __restrict__ ent,
                       float2* __restrict__ out2) {
    const int t = blockIdx.x * TPB + threadIdx.x;   // sample index, exact fit

    // 5 independent LDG.64 (MLP = 5), issued first.
    float2 v[5];
    const float2* src = inputs2 + t * 5;
    #pragma unroll
    for (int i = 0; i < 5; i++) v[i] = src[i];

    // Vectorized uniform broadcast loads of the parameter vectors.
    float r[N_QUBITS];
    {
        float4 r0 = __ldg(reinterpret_cast<const float4*>(rot));      // rot[0..3]
        float4 r1 = __ldg(reinterpret_cast<const float4*>(rot) + 1);  // rot[4..7]
        float2 r2 = __ldg(reinterpret_cast<const float2*>(rot) + 4);  // rot[8..9]
        r[0] = r0.x; r[1] = r0.y; r[2] = r0.z; r[3] = r0.w;
        r[4] = r1.x; r[5] = r1.y; r[6] = r1.z; r[7] = r1.w;
        r[8] = r2.x; r[9] = r2.y;
    }
    float ev_raw[N_QUBITS - 1];
    {
        float4 e0 = __ldg(reinterpret_cast<const float4*>(ent));      // ent[0..3]
        float4 e1 = __ldg(reinterpret_cast<const float4*>(ent) + 1);  // ent[4..7]
        float  e2 = __ldg(ent + 8);                                   // ent[8]
        ev_raw[0] = e0.x; ev_raw[1] = e0.y; ev_raw[2] = e0.z; ev_raw[3] = e0.w;
        ev_raw[4] = e1.x; ev_raw[5] = e1.y; ev_raw[6] = e1.z; ev_raw[7] = e1.w;
        ev_raw[8] = e2;
    }
    float k[N_QUBITS - 1], kc[N_QUBITS - 1];
    #pragma unroll
    for (int i = 0; i < N_QUBITS - 1; i++) {
        float kk = 0.5f - 0.5f * __cosf(ev_raw[i]);   // sin^2(e/2)
        k[i]  = kk;
        kc[i] = 1.0f - kk;
    }

    float x[N_QUBITS];
    #pragma unroll
    for (int i = 0; i < 5; i++) { x[2*i] = v[i].x; x[2*i+1] = v[i].y; }

    // All 10 cos are independent (pipelined MUFU); carry chain is
    // mul + fma per step (the minimal 2-op serial form).
    float c[N_QUBITS];
    #pragma unroll
    for (int i = 0; i < N_QUBITS; i++) c[i] = __cosf(x[i] + r[i]);

    float e[N_QUBITS];
    float carry = 1.0f;
    #pragma unroll
    for (int i = 0; i < N_QUBITS; i++) {
        float ev = c[i] * carry;
        e[i] = ev;
        if (i < N_QUBITS - 1) carry = __fmaf_rn(k[i], ev, kc[i]);
    }

    float2* dst = out2 + t * 5;
    #pragma unroll
    for (int i = 0; i < 5; i++) {
        float2 o; o.x = e[2*i]; o.y = e[2*i+1];
        dst[i] = o;
    }
}

extern "C" void kernel_launch(void* const* d_in, const int* in_sizes, int n_in,
                              void* d_out, int out_size) {
    const float* inputs = (const float*)d_in[0];  // (16, 1024, 10) fp32
    const float* rot    = (const float*)d_in[1];  // (10,)
    const float* ent    = (const float*)d_in[2];  // (9,)
    float* out = (float*)d_out;

    int total_elems = in_sizes[0];                 // 163840
    int T = total_elems / N_QUBITS;                // 16384 samples
    int blocks = T / TPB;                          // 128, exact

    qsa_closed_form_kernel<<<blocks, TPB>>>(
        reinterpret_cast<const float2*>(inputs), rot, ent,
        reinterpret_cast<float2*>(out));
}